// round 16
// baseline (speedup 1.0000x reference)
#include <cuda_runtime.h>
#include <cuda_fp16.h>
#include <math.h>
#include <stdint.h>

#define B_  32
#define S_  2048
#define H_  1024
#define BS_ (B_ * S_)

// ---------------- scratch (small device globals only) -----------------------
__device__ __align__(1024) float g_part[8 * BS_];   // per-o-block score partials (2MB)
__device__ __align__(1024) float g_bias2[B_ * H_];  // [B,H]

// =================== PTX helpers ============================================
__device__ __forceinline__ uint32_t smem_u32(const void* p) {
    uint32_t a;
    asm("{ .reg .u64 t; cvta.to.shared.u64 t, %1; cvt.u32.u64 %0, t; }"
        : "=r"(a) : "l"(p));
    return a;
}
__device__ __forceinline__ void ldsm4(uint32_t r[4], uint32_t addr) {
    asm volatile("ldmatrix.sync.aligned.m8n8.x4.shared.b16 {%0,%1,%2,%3}, [%4];"
                 : "=r"(r[0]), "=r"(r[1]), "=r"(r[2]), "=r"(r[3]) : "r"(addr));
}
__device__ __forceinline__ void mma16816(float c[4], const uint32_t a[4],
                                         uint32_t b0, uint32_t b1) {
    asm volatile(
        "mma.sync.aligned.m16n8k16.row.col.f32.f16.f16.f32 "
        "{%0,%1,%2,%3}, {%4,%5,%6,%7}, {%8,%9}, {%0,%1,%2,%3};"
        : "+f"(c[0]), "+f"(c[1]), "+f"(c[2]), "+f"(c[3])
        : "r"(a[0]), "r"(a[1]), "r"(a[2]), "r"(a[3]), "r"(b0), "r"(b1));
}
__device__ __forceinline__ void cp_async16(uint32_t dst, const void* src) {
    asm volatile("cp.async.cg.shared.global [%0], [%1], 16;"
                 :: "r"(dst), "l"(src) : "memory");
}
__device__ __forceinline__ void cp_commit() {
    asm volatile("cp.async.commit_group;" ::: "memory");
}
__device__ __forceinline__ void cp_wait0() {
    asm volatile("cp.async.wait_group 0;" ::: "memory");
}

// fp16 rn split of one float4: xh = rn_f16(x), xl = rn_f16(x - xh).
// dst_hi = hi-plane location; lo plane is +8192 bytes.
__device__ __forceinline__ void split_store_f16(const float4 val, char* dst_hi) {
    const __half h0 = __float2half_rn(val.x);
    const __half h1 = __float2half_rn(val.y);
    const __half h2 = __float2half_rn(val.z);
    const __half h3 = __float2half_rn(val.w);
    __half2 hw0 = __halves2half2(h0, h1);
    __half2 hw1 = __halves2half2(h2, h3);
    const __half l0 = __float2half_rn(val.x - __half2float(h0));
    const __half l1 = __float2half_rn(val.y - __half2float(h1));
    const __half l2 = __float2half_rn(val.z - __half2float(h2));
    const __half l3 = __float2half_rn(val.w - __half2float(h3));
    __half2 lw0 = __halves2half2(l0, l1);
    __half2 lw1 = __halves2half2(l2, l3);
    ((__half2*)dst_hi)[0] = hw0;
    ((__half2*)dst_hi)[1] = hw1;
    ((__half2*)(dst_hi + 8192))[0] = lw0;
    ((__half2*)(dst_hi + 8192))[1] = lw1;
}

// single-plane fp16 rn convert of one float4
__device__ __forceinline__ void cvt_store_f16(const float4 val, char* dst) {
    __half2 w0 = __halves2half2(__float2half_rn(val.x), __float2half_rn(val.y));
    __half2 w1 = __halves2half2(__float2half_rn(val.z), __float2half_rn(val.w));
    ((__half2*)dst)[0] = w0;
    ((__half2*)dst)[1] = w1;
}

// ---------------- SMEM layout for energy_mma --------------------------------
// bias 0..512 | v 512..1024 | B fp32 slots 1024..17408 |
// fp16 double buffer @17408: 2 x 24KB (AH 0 | AL 8K | BH 16K)
#define SM_BIAS   0
#define SM_V      512
#define SM_F32    1024
#define SM_BF     17408
#define BF_BUF    24576
#define BF_BH     16384
#define SM_TOTAL  (SM_BF + 2 * BF_BUF)    // 66560 -> 2 CTAs/SM

// ---------------- kernel 1: bias2 = hidden @ W^T + b_attn (R11 version) -----
__global__ void bias2_kernel(const float* __restrict__ hidden,
                             const float* __restrict__ W,
                             const float* __restrict__ b_attn) {
    __shared__ float sh[H_];
    const int b = blockIdx.x;
    for (int i = threadIdx.x; i < H_; i += blockDim.x) sh[i] = hidden[b * H_ + i];
    __syncthreads();

    const int w    = threadIdx.x >> 5;
    const int lane = threadIdx.x & 31;
    const int o    = blockIdx.y * 8 + w;
    const float* wr = W + (size_t)o * H_;

    float sum = 0.0f;
#pragma unroll
    for (int h = lane * 4; h < H_; h += 128) {
        float4 wv = *(const float4*)(wr + h);
        float4 xv = *(const float4*)(sh + h);
        sum += wv.x * xv.x + wv.y * xv.y + wv.z * xv.z + wv.w * xv.w;
    }
#pragma unroll
    for (int off = 16; off; off >>= 1)
        sum += __shfl_xor_sync(0xffffffffu, sum, off);
    if (lane == 0) g_bias2[b * H_ + o] = sum + b_attn[o];
}

// ---------------- kernel 2: fp16 2-product split GEMM + tanh + dot(v) -------
// part[oblk][b,s] = sum_{o in oblk} v[o]*tanh(enc[s]·W[o] + bias2[b,o])
// Hot loop identical to R11/R15 (frozen); only the epilogue differs:
// smem cross-warp reduction + plain stores (no global atomics, no zero pass).
__device__ __forceinline__ float fast_tanh(float x) {
    float t = __expf(-2.0f * fabsf(x));
    float r = __fdividef(1.0f - t, 1.0f + t);
    return copysignf(r, x);
}

__global__ void __launch_bounds__(256, 2)
energy_mma(const float* __restrict__ enc, const float* __restrict__ W,
           const float* __restrict__ v) {
    extern __shared__ __align__(1024) char smem[];
    const uint32_t sb  = smem_u32(smem);
    const int tid  = threadIdx.x;
    const int wid  = tid >> 5;
    const int lane = tid & 31;
    const int oBase   = blockIdx.x * 128;
    const int rowBase = blockIdx.y * 128;
    const int b       = rowBase >> 11;

    const int warpM = (wid >> 2) * 64;
    const int warpN = (wid & 3) * 32;

    if (tid < 128) {
        ((float*)(smem + SM_BIAS))[tid] = g_bias2[b * H_ + oBase + tid];
        ((float*)(smem + SM_V))[tid]    = v[oBase + tid];
    }

    // ---- loader mapping: 8 threads/row, 32 rows/pass, 4 passes
    const int crow = tid >> 3;           // 0..31
    const int cf   = tid & 7;            // float4 index within 32-float chunk
    const float* aSrc = enc + (size_t)(rowBase + crow) * H_ + cf * 4;
    const float* bSrc = W   + (size_t)(oBase  + crow) * H_ + cf * 4;
#define SLOT(j) (sb + SM_F32 + ((((j) << 8) + tid) << 4))
    uint32_t dOff[4];
#pragma unroll
    for (int p = 0; p < 4; ++p) {
        const int row = p * 32 + crow;
        dOff[p] = row * 64 + (((cf >> 1) ^ ((row >> 1) & 3)) << 4) + (cf & 1) * 8;
    }

    // A chunk prefetch registers (live across one MMA block)
    float4 areg[4];

#define LDG_A(c)                                                               \
    do {                                                                       \
        _Pragma("unroll")                                                      \
        for (int p = 0; p < 4; ++p)                                            \
            areg[p] = *(const float4*)(aSrc + (size_t)p * 32 * H_ + (c) * 32); \
    } while (0)

#define CP_B(c)                                                                \
    do {                                                                       \
        _Pragma("unroll")                                                      \
        for (int p = 0; p < 4; ++p)                                            \
            cp_async16(SLOT(p), bSrc + (size_t)p * 32 * H_ + (c) * 32);        \
        cp_commit();                                                           \
    } while (0)

    // convert A (from regs, 2 planes) + B (from slots, 1 plane) into buffer
#define CONVERT(bufsel)                                                        \
    do {                                                                       \
        char* _buf = (char*)smem + SM_BF + (bufsel) * BF_BUF;                  \
        cp_wait0();                                                            \
        _Pragma("unroll")                                                      \
        for (int p = 0; p < 4; ++p) split_store_f16(areg[p], _buf + dOff[p]);  \
        _Pragma("unroll")                                                      \
        for (int j = 0; j < 4; ++j) {                                          \
            float4 bx;                                                         \
            asm volatile("ld.shared.v4.b32 {%0,%1,%2,%3}, [%4];"               \
                : "=f"(bx.x), "=f"(bx.y), "=f"(bx.z), "=f"(bx.w)               \
                : "r"(SLOT(j)));                                               \
            cvt_store_f16(bx, _buf + BF_BH + dOff[j]);                         \
        }                                                                      \
    } while (0)

    // ---- mma fragment mapping (validated R6-R15)
    const int rA = (lane & 7) + (((lane >> 3) & 1) << 3);
    const int gA = (lane >> 4) & 1;
    const int rB = (lane & 7) + (((lane >> 4) & 1) << 3);
    const int gB = (lane >> 3) & 1;
    const int xA2 = (rA >> 1) & 3;
    const int xB2 = (rB >> 1) & 3;

    float acc[4][4][4];
#pragma unroll
    for (int i = 0; i < 4; ++i)
#pragma unroll
        for (int j = 0; j < 4; ++j)
#pragma unroll
            for (int k = 0; k < 4; ++k) acc[i][j][k] = 0.0f;

    // ---- prologue: chunk 0 converted into buf 0; chunk 1 in flight
    CP_B(0);
    LDG_A(0);
    CONVERT(0);
    CP_B(1);
    LDG_A(1);
    __syncthreads();

#pragma unroll 1
    for (int kt = 0; kt < 32; ++kt) {
        // mma on fp16 buf kt&1 (ready; synced). areg holds chunk kt+1.
        {
            const uint32_t bufb = sb + SM_BF + (kt & 1) * BF_BUF;
            const uint32_t AH = bufb;
            const uint32_t AL = bufb + 8192;
            const uint32_t BH = bufb + BF_BH;
#pragma unroll
            for (int k16 = 0; k16 < 2; ++k16) {
                const int cA = ((2 * k16 + gA) ^ xA2) << 4;
                const int cB = ((2 * k16 + gB) ^ xB2) << 4;
                uint32_t ah[4][4], bh[2][4];
#pragma unroll
                for (int mi = 0; mi < 4; ++mi)
                    ldsm4(ah[mi], AH + (warpM + mi * 16 + rA) * 64 + cA);
#pragma unroll
                for (int np = 0; np < 2; ++np)
                    ldsm4(bh[np], BH + (warpN + np * 16 + rB) * 64 + cB);
                // product 1: xh * wh
#pragma unroll
                for (int mi = 0; mi < 4; ++mi)
#pragma unroll
                    for (int ni = 0; ni < 4; ++ni)
                        mma16816(acc[mi][ni], ah[mi],
                                 bh[ni >> 1][(ni & 1) * 2], bh[ni >> 1][(ni & 1) * 2 + 1]);
                // product 2: xl * wh (al reuses ah's registers)
                uint32_t al[4][4];
#pragma unroll
                for (int mi = 0; mi < 4; ++mi)
                    ldsm4(al[mi], AL + (warpM + mi * 16 + rA) * 64 + cA);
#pragma unroll
                for (int mi = 0; mi < 4; ++mi)
#pragma unroll
                    for (int ni = 0; ni < 4; ++ni)
                        mma16816(acc[mi][ni], al[mi],
                                 bh[ni >> 1][(ni & 1) * 2], bh[ni >> 1][(ni & 1) * 2 + 1]);
            }
        }

        // convert chunk kt+1 into buf (kt+1)&1, then start chunk kt+2 loads
        if (kt + 1 < 32) CONVERT((kt + 1) & 1);
        if (kt + 2 < 32) {
            CP_B(kt + 2);
            LDG_A(kt + 2);
        }
        __syncthreads();
    }

    // ---- epilogue: tanh(acc + bias2)*v, reduce over n (quad shuffle +
    // cross-warp smem), plain stores to g_part (no global atomics) ----------
    const float* sbias = (const float*)(smem + SM_BIAS);
    const float* sv    = (const float*)(smem + SM_V);
    float* sred        = (float*)(smem + SM_F32);   // slots are idle now
    const int q = lane & 3;
    const int r = lane >> 2;

    if (tid < 128) sred[tid] = 0.0f;
    __syncthreads();

#pragma unroll
    for (int mi = 0; mi < 4; ++mi) {
        float pa = 0.0f, pb = 0.0f;
#pragma unroll
        for (int ni = 0; ni < 4; ++ni) {
            const int n0 = warpN + ni * 8 + 2 * q;
            const float b0 = sbias[n0], b1 = sbias[n0 + 1];
            const float v0 = sv[n0],    v1 = sv[n0 + 1];
            pa += fast_tanh(acc[mi][ni][0] + b0) * v0 +
                  fast_tanh(acc[mi][ni][1] + b1) * v1;
            pb += fast_tanh(acc[mi][ni][2] + b0) * v0 +
                  fast_tanh(acc[mi][ni][3] + b1) * v1;
        }
        pa += __shfl_xor_sync(0xffffffffu, pa, 1);
        pa += __shfl_xor_sync(0xffffffffu, pa, 2);
        pb += __shfl_xor_sync(0xffffffffu, pb, 1);
        pb += __shfl_xor_sync(0xffffffffu, pb, 2);
        if (q == 0) {
            const int m = warpM + mi * 16 + r;     // 4 warpN-warps accumulate
            atomicAdd(&sred[m], pa);               // in smem (fast, local)
            atomicAdd(&sred[m + 8], pb);
        }
    }
    __syncthreads();
    if (tid < 128)
        g_part[(size_t)blockIdx.x * BS_ + rowBase + tid] = sred[tid];
}

// ---------------- kernel 3: softmax over S (sums the 8 o-block partials) ----
__global__ void softmax_kernel(float* __restrict__ attn) {
    __shared__ float red[8];
    const int b = blockIdx.x, t = threadIdx.x;

    float loc[8];
    float mx = -1e30f;
#pragma unroll
    for (int i = 0; i < 8; ++i) {
        const int idx = b * S_ + t + i * 256;
        float s = 0.0f;
#pragma unroll
        for (int p = 0; p < 8; ++p) s += g_part[p * BS_ + idx];
        loc[i] = s;
        mx = fmaxf(mx, s);
    }
#pragma unroll
    for (int off = 16; off; off >>= 1)
        mx = fmaxf(mx, __shfl_xor_sync(0xffffffffu, mx, off));
    if ((t & 31) == 0) red[t >> 5] = mx;
    __syncthreads();
    float bm = red[0];
#pragma unroll
    for (int w = 1; w < 8; ++w) bm = fmaxf(bm, red[w]);
    __syncthreads();

    float sum = 0.0f;
#pragma unroll
    for (int i = 0; i < 8; ++i) {
        loc[i] = expf(loc[i] - bm);
        sum += loc[i];
    }
#pragma unroll
    for (int off = 16; off; off >>= 1)
        sum += __shfl_xor_sync(0xffffffffu, sum, off);
    if ((t & 31) == 0) red[t >> 5] = sum;
    __syncthreads();
    float bs = 0.0f;
#pragma unroll
    for (int w = 0; w < 8; ++w) bs += red[w];

    const float inv = 1.0f / bs;
#pragma unroll
    for (int i = 0; i < 8; ++i)
        attn[b * S_ + t + i * 256] = loc[i] * inv;
}

// ---------------- kernel 4: context = attn @ enc (atomic-free) --------------
// grid (B, 8): block owns 128 h-values; 8 s-stripes x 32 float4 columns.
__global__ void context_kernel(const float* __restrict__ enc,
                               const float* __restrict__ attn,
                               float* __restrict__ ctx) {
    __shared__ float ws[S_];
    __shared__ float4 part[8][32];
    const int b  = blockIdx.x;
    const int h0 = blockIdx.y * 128;
    const int st = threadIdx.x >> 5;     // s-stripe 0..7
    const int c  = threadIdx.x & 31;     // float4 column 0..31

    for (int i = threadIdx.x; i < S_; i += 256) ws[i] = attn[b * S_ + i];
    __syncthreads();

    float4 acc = make_float4(0.f, 0.f, 0.f, 0.f);
    const float* base = enc + (size_t)b * S_ * H_ + h0 + c * 4;
#pragma unroll 4
    for (int s = st; s < S_; s += 8) {
        const float w = ws[s];
        float4 e = *(const float4*)(base + (size_t)s * H_);
        acc.x += w * e.x;  acc.y += w * e.y;
        acc.z += w * e.z;  acc.w += w * e.w;
    }
    part[st][c] = acc;
    __syncthreads();

    if (threadIdx.x < 32) {
        float4 s = part[0][threadIdx.x];
#pragma unroll
        for (int p = 1; p < 8; ++p) {
            float4 t = part[p][threadIdx.x];
            s.x += t.x;  s.y += t.y;  s.z += t.z;  s.w += t.w;
        }
        *(float4*)(ctx + b * H_ + h0 + threadIdx.x * 4) = s;
    }
}

// ---------------- launch ----------------------------------------------------
extern "C" void kernel_launch(void* const* d_in, const int* in_sizes, int n_in,
                              void* d_out, int out_size) {
    const float* hidden = (const float*)d_in[0];   // [B,H]
    const float* enc    = (const float*)d_in[1];   // [B,S,H]
    const float* W      = (const float*)d_in[2];   // [H,H]
    const float* b_attn = (const float*)d_in[3];   // [H]
    const float* v      = (const float*)d_in[4];   // [H]

    float* out  = (float*)d_out;
    float* ctx  = out;             // [B,H]
    float* attn = out + B_ * H_;   // [B,S]

    // idempotent, executed every call (no static guards)
    cudaFuncSetAttribute((const void*)energy_mma,
                         cudaFuncAttributeMaxDynamicSharedMemorySize, SM_TOTAL);

    bias2_kernel<<<dim3(B_, H_ / 8), 256>>>(hidden, W, b_attn);
    energy_mma<<<dim3(H_ / 128, BS_ / 128), 256, SM_TOTAL>>>(enc, W, v);
    softmax_kernel<<<B_, 256>>>(attn);
    context_kernel<<<dim3(B_, 8), 256>>>(enc, attn, ctx);
}

// round 17
// speedup vs baseline: 1.0682x; 1.0682x over previous
#include <cuda_runtime.h>
#include <cuda_fp16.h>
#include <math.h>
#include <stdint.h>

#define B_  32
#define S_  2048
#define H_  1024
#define BS_ (B_ * S_)

// ---------------- scratch (small device globals only) -----------------------
__device__ __align__(1024) float g_scores[BS_];     // [B,S] logits
__device__ __align__(1024) float g_bias2[B_ * H_];  // [B,H]

// =================== PTX helpers ============================================
__device__ __forceinline__ uint32_t smem_u32(const void* p) {
    uint32_t a;
    asm("{ .reg .u64 t; cvta.to.shared.u64 t, %1; cvt.u32.u64 %0, t; }"
        : "=r"(a) : "l"(p));
    return a;
}
__device__ __forceinline__ void ldsm4(uint32_t r[4], uint32_t addr) {
    asm volatile("ldmatrix.sync.aligned.m8n8.x4.shared.b16 {%0,%1,%2,%3}, [%4];"
                 : "=r"(r[0]), "=r"(r[1]), "=r"(r[2]), "=r"(r[3]) : "r"(addr));
}
__device__ __forceinline__ void mma16816(float c[4], const uint32_t a[4],
                                         uint32_t b0, uint32_t b1) {
    asm volatile(
        "mma.sync.aligned.m16n8k16.row.col.f32.f16.f16.f32 "
        "{%0,%1,%2,%3}, {%4,%5,%6,%7}, {%8,%9}, {%0,%1,%2,%3};"
        : "+f"(c[0]), "+f"(c[1]), "+f"(c[2]), "+f"(c[3])
        : "r"(a[0]), "r"(a[1]), "r"(a[2]), "r"(a[3]), "r"(b0), "r"(b1));
}
__device__ __forceinline__ void cp_async16(uint32_t dst, const void* src) {
    asm volatile("cp.async.cg.shared.global [%0], [%1], 16;"
                 :: "r"(dst), "l"(src) : "memory");
}
__device__ __forceinline__ void cp_commit() {
    asm volatile("cp.async.commit_group;" ::: "memory");
}
__device__ __forceinline__ void cp_wait0() {
    asm volatile("cp.async.wait_group 0;" ::: "memory");
}

// fp16 rn split of one float4: xh = rn_f16(x), xl = rn_f16(x - xh).
// dst_hi = hi-plane location; lo plane is +8192 bytes.
__device__ __forceinline__ void split_store_f16(const float4 val, char* dst_hi) {
    const __half h0 = __float2half_rn(val.x);
    const __half h1 = __float2half_rn(val.y);
    const __half h2 = __float2half_rn(val.z);
    const __half h3 = __float2half_rn(val.w);
    __half2 hw0 = __halves2half2(h0, h1);
    __half2 hw1 = __halves2half2(h2, h3);
    const __half l0 = __float2half_rn(val.x - __half2float(h0));
    const __half l1 = __float2half_rn(val.y - __half2float(h1));
    const __half l2 = __float2half_rn(val.z - __half2float(h2));
    const __half l3 = __float2half_rn(val.w - __half2float(h3));
    __half2 lw0 = __halves2half2(l0, l1);
    __half2 lw1 = __halves2half2(l2, l3);
    ((__half2*)dst_hi)[0] = hw0;
    ((__half2*)dst_hi)[1] = hw1;
    ((__half2*)(dst_hi + 8192))[0] = lw0;
    ((__half2*)(dst_hi + 8192))[1] = lw1;
}

// single-plane fp16 rn convert of one float4
__device__ __forceinline__ void cvt_store_f16(const float4 val, char* dst) {
    __half2 w0 = __halves2half2(__float2half_rn(val.x), __float2half_rn(val.y));
    __half2 w1 = __halves2half2(__float2half_rn(val.z), __float2half_rn(val.w));
    ((__half2*)dst)[0] = w0;
    ((__half2*)dst)[1] = w1;
}

// ---------------- SMEM layout for energy_mma --------------------------------
// bias 0..512 | v 512..1024 | B fp32 slots 1024..17408 |
// fp16 double buffer @17408: 2 x 24KB (AH 0 | AL 8K | BH 16K)
#define SM_BIAS   0
#define SM_V      512
#define SM_F32    1024
#define SM_BF     17408
#define BF_BUF    24576
#define BF_BH     16384
#define SM_TOTAL  (SM_BF + 2 * BF_BUF)    // 66560 -> 2 CTAs/SM

// ---------------- kernel 1: bias2 = hidden @ W^T + b_attn -------------------
// (R11/R15 version + folded zeroing of g_scores and ctx: bias2's 4096x256
//  threads cover both arrays; bias2 completes before energy/context run.)
__global__ void bias2_kernel(const float* __restrict__ hidden,
                             const float* __restrict__ W,
                             const float* __restrict__ b_attn,
                             float* __restrict__ ctx) {
    __shared__ float sh[H_];
    const int b = blockIdx.x;

    // folded zero pass (replaces zero_kernel)
    {
        const int gid = (blockIdx.x * gridDim.y + blockIdx.y) * 256 + threadIdx.x;
        if (gid < BS_)      g_scores[gid] = 0.0f;
        if (gid < B_ * H_)  ctx[gid]      = 0.0f;
    }

    for (int i = threadIdx.x; i < H_; i += blockDim.x) sh[i] = hidden[b * H_ + i];
    __syncthreads();

    const int w    = threadIdx.x >> 5;
    const int lane = threadIdx.x & 31;
    const int o    = blockIdx.y * 8 + w;
    const float* wr = W + (size_t)o * H_;

    float sum = 0.0f;
#pragma unroll
    for (int h = lane * 4; h < H_; h += 128) {
        float4 wv = *(const float4*)(wr + h);
        float4 xv = *(const float4*)(sh + h);
        sum += wv.x * xv.x + wv.y * xv.y + wv.z * xv.z + wv.w * xv.w;
    }
#pragma unroll
    for (int off = 16; off; off >>= 1)
        sum += __shfl_xor_sync(0xffffffffu, sum, off);
    if (lane == 0) g_bias2[b * H_ + o] = sum + b_attn[o];
}

// ---------------- kernel 2: fp16 2-product split GEMM + tanh + dot(v) -------
// scores[b,s] += sum_o v[o]*tanh(enc[s]·W[o] + bias2[b,o])
// x*w ~ xh*wh + xl*wh (= x*wh exactly); dropped term x*wl ~ 2^-12.
// FROZEN R11/R15 hot loop (all structural variants measured slower).
__device__ __forceinline__ float fast_tanh(float x) {
    float t = __expf(-2.0f * fabsf(x));
    float r = __fdividef(1.0f - t, 1.0f + t);
    return copysignf(r, x);
}

__global__ void __launch_bounds__(256, 2)
energy_mma(const float* __restrict__ enc, const float* __restrict__ W,
           const float* __restrict__ v) {
    extern __shared__ __align__(1024) char smem[];
    const uint32_t sb  = smem_u32(smem);
    const int tid  = threadIdx.x;
    const int wid  = tid >> 5;
    const int lane = tid & 31;
    const int oBase   = blockIdx.x * 128;
    const int rowBase = blockIdx.y * 128;
    const int b       = rowBase >> 11;

    const int warpM = (wid >> 2) * 64;
    const int warpN = (wid & 3) * 32;

    if (tid < 128) {
        ((float*)(smem + SM_BIAS))[tid] = g_bias2[b * H_ + oBase + tid];
        ((float*)(smem + SM_V))[tid]    = v[oBase + tid];
    }

    // ---- loader mapping: 8 threads/row, 32 rows/pass, 4 passes
    const int crow = tid >> 3;           // 0..31
    const int cf   = tid & 7;            // float4 index within 32-float chunk
    const float* aSrc = enc + (size_t)(rowBase + crow) * H_ + cf * 4;
    const float* bSrc = W   + (size_t)(oBase  + crow) * H_ + cf * 4;
#define SLOT(j) (sb + SM_F32 + ((((j) << 8) + tid) << 4))
    uint32_t dOff[4];
#pragma unroll
    for (int p = 0; p < 4; ++p) {
        const int row = p * 32 + crow;
        dOff[p] = row * 64 + (((cf >> 1) ^ ((row >> 1) & 3)) << 4) + (cf & 1) * 8;
    }

    // A chunk prefetch registers (live across one MMA block)
    float4 areg[4];

#define LDG_A(c)                                                               \
    do {                                                                       \
        _Pragma("unroll")                                                      \
        for (int p = 0; p < 4; ++p)                                            \
            areg[p] = *(const float4*)(aSrc + (size_t)p * 32 * H_ + (c) * 32); \
    } while (0)

#define CP_B(c)                                                                \
    do {                                                                       \
        _Pragma("unroll")                                                      \
        for (int p = 0; p < 4; ++p)                                            \
            cp_async16(SLOT(p), bSrc + (size_t)p * 32 * H_ + (c) * 32);        \
        cp_commit();                                                           \
    } while (0)

    // convert A (from regs, 2 planes) + B (from slots, 1 plane) into buffer
#define CONVERT(bufsel)                                                        \
    do {                                                                       \
        char* _buf = (char*)smem + SM_BF + (bufsel) * BF_BUF;                  \
        cp_wait0();                                                            \
        _Pragma("unroll")                                                      \
        for (int p = 0; p < 4; ++p) split_store_f16(areg[p], _buf + dOff[p]);  \
        _Pragma("unroll")                                                      \
        for (int j = 0; j < 4; ++j) {                                          \
            float4 bx;                                                         \
            asm volatile("ld.shared.v4.b32 {%0,%1,%2,%3}, [%4];"               \
                : "=f"(bx.x), "=f"(bx.y), "=f"(bx.z), "=f"(bx.w)               \
                : "r"(SLOT(j)));                                               \
            cvt_store_f16(bx, _buf + BF_BH + dOff[j]);                         \
        }                                                                      \
    } while (0)

    // ---- mma fragment mapping (validated R6-R16)
    const int rA = (lane & 7) + (((lane >> 3) & 1) << 3);
    const int gA = (lane >> 4) & 1;
    const int rB = (lane & 7) + (((lane >> 4) & 1) << 3);
    const int gB = (lane >> 3) & 1;
    const int xA2 = (rA >> 1) & 3;
    const int xB2 = (rB >> 1) & 3;

    float acc[4][4][4];
#pragma unroll
    for (int i = 0; i < 4; ++i)
#pragma unroll
        for (int j = 0; j < 4; ++j)
#pragma unroll
            for (int k = 0; k < 4; ++k) acc[i][j][k] = 0.0f;

    // ---- prologue: chunk 0 converted into buf 0; chunk 1 in flight
    CP_B(0);
    LDG_A(0);
    CONVERT(0);
    CP_B(1);
    LDG_A(1);
    __syncthreads();

#pragma unroll 1
    for (int kt = 0; kt < 32; ++kt) {
        // mma on fp16 buf kt&1 (ready; synced). areg holds chunk kt+1.
        {
            const uint32_t bufb = sb + SM_BF + (kt & 1) * BF_BUF;
            const uint32_t AH = bufb;
            const uint32_t AL = bufb + 8192;
            const uint32_t BH = bufb + BF_BH;
#pragma unroll
            for (int k16 = 0; k16 < 2; ++k16) {
                const int cA = ((2 * k16 + gA) ^ xA2) << 4;
                const int cB = ((2 * k16 + gB) ^ xB2) << 4;
                uint32_t ah[4][4], bh[2][4];
#pragma unroll
                for (int mi = 0; mi < 4; ++mi)
                    ldsm4(ah[mi], AH + (warpM + mi * 16 + rA) * 64 + cA);
#pragma unroll
                for (int np = 0; np < 2; ++np)
                    ldsm4(bh[np], BH + (warpN + np * 16 + rB) * 64 + cB);
                // product 1: xh * wh
#pragma unroll
                for (int mi = 0; mi < 4; ++mi)
#pragma unroll
                    for (int ni = 0; ni < 4; ++ni)
                        mma16816(acc[mi][ni], ah[mi],
                                 bh[ni >> 1][(ni & 1) * 2], bh[ni >> 1][(ni & 1) * 2 + 1]);
                // product 2: xl * wh (al reuses ah's registers)
                uint32_t al[4][4];
#pragma unroll
                for (int mi = 0; mi < 4; ++mi)
                    ldsm4(al[mi], AL + (warpM + mi * 16 + rA) * 64 + cA);
#pragma unroll
                for (int mi = 0; mi < 4; ++mi)
#pragma unroll
                    for (int ni = 0; ni < 4; ++ni)
                        mma16816(acc[mi][ni], al[mi],
                                 bh[ni >> 1][(ni & 1) * 2], bh[ni >> 1][(ni & 1) * 2 + 1]);
            }
        }

        // convert chunk kt+1 into buf (kt+1)&1, then start chunk kt+2 loads
        if (kt + 1 < 32) CONVERT((kt + 1) & 1);
        if (kt + 2 < 32) {
            CP_B(kt + 2);
            LDG_A(kt + 2);
        }
        __syncthreads();
    }

    // ---- epilogue: tanh(acc + bias2)*v, reduce over n, atomicAdd scores ----
    const float* sbias = (const float*)(smem + SM_BIAS);
    const float* sv    = (const float*)(smem + SM_V);
    const int q = lane & 3;
    const int r = lane >> 2;

#pragma unroll
    for (int mi = 0; mi < 4; ++mi) {
        float pa = 0.0f, pb = 0.0f;
#pragma unroll
        for (int ni = 0; ni < 4; ++ni) {
            const int n0 = warpN + ni * 8 + 2 * q;
            const float b0 = sbias[n0], b1 = sbias[n0 + 1];
            const float v0 = sv[n0],    v1 = sv[n0 + 1];
            pa += fast_tanh(acc[mi][ni][0] + b0) * v0 +
                  fast_tanh(acc[mi][ni][1] + b1) * v1;
            pb += fast_tanh(acc[mi][ni][2] + b0) * v0 +
                  fast_tanh(acc[mi][ni][3] + b1) * v1;
        }
        pa += __shfl_xor_sync(0xffffffffu, pa, 1);
        pa += __shfl_xor_sync(0xffffffffu, pa, 2);
        pb += __shfl_xor_sync(0xffffffffu, pb, 1);
        pb += __shfl_xor_sync(0xffffffffu, pb, 2);
        if (q == 0) {
            const int m = rowBase + warpM + mi * 16 + r;
            atomicAdd(&g_scores[m], pa);
            atomicAdd(&g_scores[m + 8], pb);
        }
    }
}

// ---------------- kernel 3: softmax over S per batch ------------------------
__global__ void softmax_kernel(float* __restrict__ attn) {
    __shared__ float red[8];
    const int b = blockIdx.x, t = threadIdx.x;
    const float* s = g_scores + b * S_;

    float loc[8];
    float mx = -1e30f;
#pragma unroll
    for (int i = 0; i < 8; ++i) {
        loc[i] = s[t + i * 256];
        mx = fmaxf(mx, loc[i]);
    }
#pragma unroll
    for (int off = 16; off; off >>= 1)
        mx = fmaxf(mx, __shfl_xor_sync(0xffffffffu, mx, off));
    if ((t & 31) == 0) red[t >> 5] = mx;
    __syncthreads();
    float bm = red[0];
#pragma unroll
    for (int w = 1; w < 8; ++w) bm = fmaxf(bm, red[w]);
    __syncthreads();

    float sum = 0.0f;
#pragma unroll
    for (int i = 0; i < 8; ++i) {
        loc[i] = expf(loc[i] - bm);
        sum += loc[i];
    }
#pragma unroll
    for (int off = 16; off; off >>= 1)
        sum += __shfl_xor_sync(0xffffffffu, sum, off);
    if ((t & 31) == 0) red[t >> 5] = sum;
    __syncthreads();
    float bs = 0.0f;
#pragma unroll
    for (int w = 0; w < 8; ++w) bs += red[w];

    const float inv = 1.0f / bs;
#pragma unroll
    for (int i = 0; i < 8; ++i)
        attn[b * S_ + t + i * 256] = loc[i] * inv;
}

// ---------------- kernel 4: context = attn @ enc (proven R15 form) ----------
__global__ void context_kernel(const float* __restrict__ enc,
                               const float* __restrict__ attn,
                               float* __restrict__ ctx) {
    __shared__ float ws[128];
    const int b  = blockIdx.x;
    const int s0 = blockIdx.y * 128;
    if (threadIdx.x < 128) ws[threadIdx.x] = attn[b * S_ + s0 + threadIdx.x];
    __syncthreads();

    const int h = threadIdx.x * 4;
    float4 acc = make_float4(0.f, 0.f, 0.f, 0.f);
    const float* base = enc + ((size_t)b * S_ + s0) * H_ + h;
#pragma unroll 8
    for (int s = 0; s < 128; ++s) {
        const float w = ws[s];
        float4 e = *(const float4*)(base + (size_t)s * H_);
        acc.x += w * e.x;  acc.y += w * e.y;
        acc.z += w * e.z;  acc.w += w * e.w;
    }
    atomicAdd(&ctx[b * H_ + h + 0], acc.x);
    atomicAdd(&ctx[b * H_ + h + 1], acc.y);
    atomicAdd(&ctx[b * H_ + h + 2], acc.z);
    atomicAdd(&ctx[b * H_ + h + 3], acc.w);
}

// ---------------- launch ----------------------------------------------------
extern "C" void kernel_launch(void* const* d_in, const int* in_sizes, int n_in,
                              void* d_out, int out_size) {
    const float* hidden = (const float*)d_in[0];   // [B,H]
    const float* enc    = (const float*)d_in[1];   // [B,S,H]
    const float* W      = (const float*)d_in[2];   // [H,H]
    const float* b_attn = (const float*)d_in[3];   // [H]
    const float* v      = (const float*)d_in[4];   // [H]

    float* out  = (float*)d_out;
    float* ctx  = out;             // [B,H]
    float* attn = out + B_ * H_;   // [B,S]

    // idempotent, executed every call (no static guards)
    cudaFuncSetAttribute((const void*)energy_mma,
                         cudaFuncAttributeMaxDynamicSharedMemorySize, SM_TOTAL);

    bias2_kernel<<<dim3(B_, H_ / 8), 256>>>(hidden, W, b_attn, ctx);
    energy_mma<<<dim3(H_ / 128, BS_ / 128), 256, SM_TOTAL>>>(enc, W, v);
    softmax_kernel<<<B_, 256>>>(attn);
    context_kernel<<<dim3(B_, 16), 256>>>(enc, attn, ctx);
}